// round 6
// baseline (speedup 1.0000x reference)
#include <cuda_runtime.h>
#include <cuda_fp16.h>
#include <cstdint>

#define T_STEPS 2048
#define BATCH   128
#define DIM     100
#define HID     1024
#define NBLK    128
#define JT      8           // H columns per block
#define NTH     256
#define KC      128         // k-halfs per chunk
#define XW      128         // padded x width (100 -> 128)
#define NSLOT   5           // 4 rotating h slots + 1 x slot
#define SLOT_X  4
#define APITCH_B 272        // bytes per A row (128 halfs + 8 pad); ldsm conflict-free
#define AW_B    (16*APITCH_B)                 // 4352 B: one slot (16 rows)
#define WPITCH_H 1160       // halfs per W row (1152 + 8 pad)
#define WPITCH_B 2320
#define SMEM_W_OFF   (8*NSLOT*AW_B)           // 174080
#define SMEM_BIAS_OFF (SMEM_W_OFF + JT*WPITCH_B)  // 192640
#define SMEM_TOTAL   (SMEM_BIAS_OFF + 64)

// ---------------- device scratch ----------------
__device__ __half g_xT[(size_t)(T_STEPS + 1) * BATCH * XW]; // +1 zero-padded step
__device__ __half g_h[3][BATCH * HID];                 // triple-buffered hidden state
__device__ float  g_hlast[BATCH * HID];
__device__ unsigned g_cnt[8 * 32];                     // [warp-band w][group g]: w*32+g
__device__ unsigned g_bar_count;
__device__ unsigned g_bar_gen;

// ---------------- PTX helpers ----------------
__device__ __forceinline__ void cp16(uint32_t dst, const void* src) {
    asm volatile("cp.async.cg.shared.global [%0], [%1], 16;\n" :: "r"(dst), "l"(src) : "memory");
}
__device__ __forceinline__ void cp_commit() {
    asm volatile("cp.async.commit_group;\n" ::: "memory");
}
template <int N>
__device__ __forceinline__ void cp_wait() {
    asm volatile("cp.async.wait_group %0;\n" :: "n"(N) : "memory");
}
__device__ __forceinline__ void ldsm_x4(uint32_t addr, uint32_t& r0, uint32_t& r1, uint32_t& r2, uint32_t& r3) {
    asm volatile("ldmatrix.sync.aligned.m8n8.x4.shared.b16 {%0,%1,%2,%3}, [%4];\n"
                 : "=r"(r0), "=r"(r1), "=r"(r2), "=r"(r3) : "r"(addr));
}
__device__ __forceinline__ void ldsm_x2(uint32_t addr, uint32_t& r0, uint32_t& r1) {
    asm volatile("ldmatrix.sync.aligned.m8n8.x2.shared.b16 {%0,%1}, [%2];\n"
                 : "=r"(r0), "=r"(r1) : "r"(addr));
}
__device__ __forceinline__ void mma16816(float* c, uint32_t a0, uint32_t a1, uint32_t a2, uint32_t a3,
                                         uint32_t b0, uint32_t b1) {
    asm volatile("mma.sync.aligned.m16n8k16.row.col.f32.f16.f16.f32 "
                 "{%0,%1,%2,%3},{%4,%5,%6,%7},{%8,%9},{%0,%1,%2,%3};\n"
                 : "+f"(c[0]), "+f"(c[1]), "+f"(c[2]), "+f"(c[3])
                 : "r"(a0), "r"(a1), "r"(a2), "r"(a3), "r"(b0), "r"(b1));
}
__device__ __forceinline__ unsigned ld_acq(const unsigned* p) {
    unsigned v;
    asm volatile("ld.acquire.gpu.u32 %0, [%1];" : "=r"(v) : "l"(p) : "memory");
    return v;
}

// ---------------- grid barrier (init/final only) ----------------
__device__ __forceinline__ void grid_barrier() {
    __syncthreads();
    if (threadIdx.x == 0) {
        unsigned my = *(volatile unsigned*)&g_bar_gen;
        __threadfence();
        unsigned a = atomicAdd(&g_bar_count, 1u);
        if (a == NBLK - 1) {
            *(volatile unsigned*)&g_bar_count = 0u;
            __threadfence();
            atomicAdd(&g_bar_gen, 1u);
        } else {
            while (*(volatile unsigned*)&g_bar_gen == my) { __nanosleep(40); }
        }
        __threadfence();
    }
    __syncthreads();
}

// ---------------- kernel 1: transpose/pad x to fp16 (+1 zero step) ----------------
__global__ void __launch_bounds__(256) xform_kernel(const float* __restrict__ x) {
    int t = blockIdx.x;
    const float* xs = x + (size_t)t * BATCH * DIM;
    __half* o = g_xT + (size_t)t * BATCH * XW;
    for (int i = threadIdx.x; i < BATCH * XW; i += 256) {
        int b = i >> 7, k = i & 127;
        float v = (t < T_STEPS && k < DIM) ? xs[b * DIM + k] : 0.0f;
        o[i] = __float2half_rn(v);
    }
}

// ---------------- kernel 2: persistent RNN, 128 SMs, warp-decoupled ----------------
__global__ void __launch_bounds__(NTH, 1)
rnn_kernel(const float* __restrict__ W_ih, const float* __restrict__ b_ih,
           const float* __restrict__ W_hh, const float* __restrict__ b_hh,
           const float* __restrict__ W_out, const float* __restrict__ b_out,
           float* __restrict__ out)
{
    extern __shared__ char smem[];
    __half* sW    = (__half*)(smem + SMEM_W_OFF);
    float*  sBias = (float*)(smem + SMEM_BIAS_OFF);

    const int tid  = threadIdx.x;
    const int blk  = blockIdx.x;
    const int j0   = blk * JT;
    const int lane = tid & 31;
    const int warp = tid >> 5;

    // ---- prologue: W slice fp16 (zero pads first) ----
    for (int i = tid; i < (JT * WPITCH_B) / 4; i += NTH)
        ((uint32_t*)sW)[i] = 0u;
    __syncthreads();
    for (int i = tid; i < JT * HID; i += NTH) {
        int n = i >> 10, k = i & 1023;
        sW[n * WPITCH_H + k] = __float2half_rn(W_hh[(j0 + n) * HID + k]);
    }
    for (int i = tid; i < JT * DIM; i += NTH) {
        int n = i / DIM, d = i % DIM;
        sW[n * WPITCH_H + HID + d] = __float2half_rn(W_ih[(j0 + n) * DIM + d]);
    }
    if (tid < JT) sBias[tid] = b_ih[j0 + tid] + b_hh[j0 + tid];

    // zero h buffer 0: 16384 uint4 over 32768 threads
    {
        int i = blk * NTH + tid;
        if (i < (BATCH * HID) / 8) {
            uint4 z = make_uint4(0u, 0u, 0u, 0u);
            ((uint4*)g_h[0])[i] = z;
        }
    }
    grid_barrier();

    // ---- per-warp geometry: warp owns batch rows [16w,16w+16), cols [j0,j0+8) ----
    uint32_t smem_u = (uint32_t)__cvta_generic_to_shared(smem);
    const uint32_t aslot = smem_u + warp * (NSLOT * AW_B);
    const uint32_t aoff = (lane & 15) * APITCH_B + ((lane >> 4) * 16);
    const uint32_t boff = smem_u + SMEM_W_OFF
        + (lane & 7) * WPITCH_B + (((lane >> 3) & 1) * 16);

    const int er  = lane >> 2;            // epilogue row within m16
    const int ecc = (lane & 3) * 2;       // epilogue col pair
    const int grow = 16 * warp;           // global batch row base
    const int jc  = j0 + ecc;
    const int gp  = blk >> 4;             // producer group of this block (16 blocks/group)
    unsigned* mycnt = &g_cnt[warp * 32 + gp];
    const unsigned* pollbase = &g_cnt[warp * 32];

    const float bia0 = sBias[ecc], bib0 = sBias[ecc + 1];

    // issue x_0 into SLOT_X
    {
        const __half* hx = g_xT + grow * XW;
        #pragma unroll
        for (int i = 0; i < 8; ++i) {
            int lin = i * 32 + lane;
            int row = lin >> 4, cc = lin & 15;
            cp16(aslot + SLOT_X * AW_B + row * APITCH_B + cc * 16, hx + row * XW + cc * 8);
        }
        cp_commit();
    }

    // ---- time loop: no block-level sync, ONE poll per step ----
    for (int t = 0; t < T_STEPS; ++t) {
        const __half* hrow = g_h[t % 3] + grow * HID;
        __half* hnxt = g_h[(t + 1) % 3];

        float acc[8];
        #pragma unroll
        for (int i = 0; i < 8; ++i) acc[i] = 0.0f;

        // compute x chunk (resident from prefetch); overlaps upcoming poll latency
        cp_wait<0>();
        {
            uint32_t ab = aslot + SLOT_X * AW_B + aoff;
            uint32_t bb = boff + HID * 2;
            #pragma unroll
            for (int s = 0; s < 8; ++s) {
                uint32_t a0, a1, a2, a3, b0, b1;
                ldsm_x2(bb + s * 32, b0, b1);
                ldsm_x4(ab + s * 32, a0, a1, a2, a3);
                mma16816(acc + (s & 1) * 4, a0, a1, a2, a3, b0, b1);
            }
        }

        // single aggregated poll: all 8 producer groups of band `warp`, step t-1 done
        if (t > 0) {
            const unsigned tgt = 16u * (unsigned)t;
            unsigned v;
            do {
                v = (lane < 8) ? ld_acq(pollbase + lane) : tgt;
            } while (!__all_sync(0xFFFFFFFFu, v >= tgt));
        }

        // issue h groups 0..3 into slots 0..3
        #pragma unroll
        for (int g = 0; g < 4; ++g) {
            const __half* src = hrow + g * KC;
            uint32_t sb = aslot + g * AW_B;
            #pragma unroll
            for (int i = 0; i < 8; ++i) {
                int lin = i * 32 + lane;
                int row = lin >> 4, cc = lin & 15;
                cp16(sb + row * APITCH_B + cc * 16, src + row * HID + cc * 8);
            }
            cp_commit();
        }

        // compute h0..h7; prefetch h4..h7 and x_{t+1} along the way
        #pragma unroll
        for (int g = 0; g < 8; ++g) {
            if (g <= 5)      cp_wait<3>();
            else if (g == 6) cp_wait<2>();
            else             cp_wait<1>();

            uint32_t ab = aslot + (g & 3) * AW_B + aoff;
            uint32_t bb = boff + g * 256;
            #pragma unroll
            for (int s = 0; s < 8; ++s) {
                uint32_t a0, a1, a2, a3, b0, b1;
                ldsm_x2(bb + s * 32, b0, b1);
                ldsm_x4(ab + s * 32, a0, a1, a2, a3);
                mma16816(acc + (s & 1) * 4, a0, a1, a2, a3, b0, b1);
            }

            if (g < 4) {
                const int gn = g + 4;
                const __half* src = hrow + gn * KC;
                uint32_t sb = aslot + (gn & 3) * AW_B;
                #pragma unroll
                for (int i = 0; i < 8; ++i) {
                    int lin = i * 32 + lane;
                    int row = lin >> 4, cc = lin & 15;
                    cp16(sb + row * APITCH_B + cc * 16, src + row * HID + cc * 8);
                }
                cp_commit();
            } else if (g == 4) {
                const __half* hx = g_xT + (size_t)(t + 1) * (BATCH * XW) + grow * XW;
                #pragma unroll
                for (int i = 0; i < 8; ++i) {
                    int lin = i * 32 + lane;
                    int row = lin >> 4, cc = lin & 15;
                    cp16(aslot + SLOT_X * AW_B + row * APITCH_B + cc * 16, hx + row * XW + cc * 8);
                }
                cp_commit();
            }
        }

        // ---- epilogue: merge split chains, bias + tanh + fp16 store ----
        {
            int row = grow + er;
            float h0 = tanhf(acc[0] + acc[4] + bia0);
            float h1 = tanhf(acc[1] + acc[5] + bib0);
            float h2 = tanhf(acc[2] + acc[6] + bia0);
            float h3 = tanhf(acc[3] + acc[7] + bib0);
            *reinterpret_cast<__half2*>(&hnxt[row * HID + jc])       = __floats2half2_rn(h0, h1);
            *reinterpret_cast<__half2*>(&hnxt[(row + 8) * HID + jc]) = __floats2half2_rn(h2, h3);
            if (t == T_STEPS - 1) {
                g_hlast[row * HID + jc]           = h0;
                g_hlast[row * HID + jc + 1]       = h1;
                g_hlast[(row + 8) * HID + jc]     = h2;
                g_hlast[(row + 8) * HID + jc + 1] = h3;
            }
        }

        // publish this warp's band of step t
        __syncwarp();
        if (lane == 0) {
            asm volatile("red.release.gpu.global.add.u32 [%0], %1;"
                         :: "l"(mycnt), "r"(1u) : "memory");
        }
    }

    // ---- drain, reset counters, readout ----
    grid_barrier();
    if (blk == 0) {
        g_cnt[tid] = 0u;   // 256 threads cover all 256 counter words
        for (int b = warp; b < BATCH; b += 8) {
            float a = 0.0f;
            #pragma unroll 4
            for (int j = lane; j < HID; j += 32)
                a += g_hlast[b * HID + j] * W_out[j];
            #pragma unroll
            for (int o = 16; o; o >>= 1) a += __shfl_xor_sync(0xFFFFFFFFu, a, o);
            if (lane == 0) out[b] = tanhf(a + b_out[0]);
        }
    }
}

// ---------------- launch ----------------
extern "C" void kernel_launch(void* const* d_in, const int* in_sizes, int n_in,
                              void* d_out, int out_size) {
    const float* x     = (const float*)d_in[0];
    const float* W_ih  = (const float*)d_in[1];
    const float* b_ih  = (const float*)d_in[2];
    const float* W_hh  = (const float*)d_in[3];
    const float* b_hh  = (const float*)d_in[4];
    const float* W_out = (const float*)d_in[5];
    const float* b_out = (const float*)d_in[6];

    cudaFuncSetAttribute(rnn_kernel, cudaFuncAttributeMaxDynamicSharedMemorySize, SMEM_TOTAL);

    xform_kernel<<<T_STEPS + 1, 256>>>(x);
    rnn_kernel<<<NBLK, NTH, SMEM_TOTAL>>>(W_ih, b_ih, W_hh, b_hh, W_out, b_out, (float*)d_out);
}

// round 7
// speedup vs baseline: 1.0257x; 1.0257x over previous
#include <cuda_runtime.h>
#include <cuda_fp16.h>
#include <cstdint>

#define T_STEPS 2048
#define BATCH   128
#define DIM     100
#define HID     1024
#define NBLK    64
#define JT      16          // H columns per block
#define NTH     256
#define KC      128         // k-halfs per chunk
#define XW      128         // padded x width (100 -> 128)
#define NSLOT   5           // 4 rotating h slots + 1 x slot
#define SLOT_X  4
#define APITCH_B 272        // bytes per A row (128 halfs + 8 pad); ldsm conflict-free
#define AW_B    (16*APITCH_B)                 // 4352 B: one slot (16 rows)
#define WPITCH_H 1160       // halfs per W row (1152 + 8 pad)
#define WPITCH_B 2320
#define SMEM_W_OFF   (8*NSLOT*AW_B)           // 174080
#define SMEM_BIAS_OFF (SMEM_W_OFF + JT*WPITCH_B)  // 211200
#define SMEM_TOTAL   (SMEM_BIAS_OFF + 64)

// ---------------- device scratch ----------------
__device__ __half g_xT[(size_t)(T_STEPS + 1) * BATCH * XW]; // +1 zero-padded step
__device__ __half g_h[3][BATCH * HID];                 // triple-buffered hidden state
__device__ float  g_hlast[BATCH * HID];
__device__ unsigned g_cnt[8 * 32];                     // [warp-band w][group g]: w*32+g
__device__ unsigned g_bar_count;
__device__ unsigned g_bar_gen;

// ---------------- PTX helpers ----------------
__device__ __forceinline__ void cp16(uint32_t dst, const void* src) {
    asm volatile("cp.async.cg.shared.global [%0], [%1], 16;\n" :: "r"(dst), "l"(src) : "memory");
}
__device__ __forceinline__ void cp_commit() {
    asm volatile("cp.async.commit_group;\n" ::: "memory");
}
template <int N>
__device__ __forceinline__ void cp_wait() {
    asm volatile("cp.async.wait_group %0;\n" :: "n"(N) : "memory");
}
__device__ __forceinline__ void ldsm_x4(uint32_t addr, uint32_t& r0, uint32_t& r1, uint32_t& r2, uint32_t& r3) {
    asm volatile("ldmatrix.sync.aligned.m8n8.x4.shared.b16 {%0,%1,%2,%3}, [%4];\n"
                 : "=r"(r0), "=r"(r1), "=r"(r2), "=r"(r3) : "r"(addr));
}
__device__ __forceinline__ void mma16816(float* c, uint32_t a0, uint32_t a1, uint32_t a2, uint32_t a3,
                                         uint32_t b0, uint32_t b1) {
    asm volatile("mma.sync.aligned.m16n8k16.row.col.f32.f16.f16.f32 "
                 "{%0,%1,%2,%3},{%4,%5,%6,%7},{%8,%9},{%0,%1,%2,%3};\n"
                 : "+f"(c[0]), "+f"(c[1]), "+f"(c[2]), "+f"(c[3])
                 : "r"(a0), "r"(a1), "r"(a2), "r"(a3), "r"(b0), "r"(b1));
}
__device__ __forceinline__ unsigned ld_acq(const unsigned* p) {
    unsigned v;
    asm volatile("ld.acquire.gpu.u32 %0, [%1];" : "=r"(v) : "l"(p) : "memory");
    return v;
}

// ---------------- grid barrier (init/final only) ----------------
__device__ __forceinline__ void grid_barrier() {
    __syncthreads();
    if (threadIdx.x == 0) {
        unsigned my = *(volatile unsigned*)&g_bar_gen;
        __threadfence();
        unsigned a = atomicAdd(&g_bar_count, 1u);
        if (a == NBLK - 1) {
            *(volatile unsigned*)&g_bar_count = 0u;
            __threadfence();
            atomicAdd(&g_bar_gen, 1u);
        } else {
            while (*(volatile unsigned*)&g_bar_gen == my) { __nanosleep(40); }
        }
        __threadfence();
    }
    __syncthreads();
}

// ---------------- kernel 1: transpose/pad x to fp16 (+1 zero step) ----------------
__global__ void __launch_bounds__(256) xform_kernel(const float* __restrict__ x) {
    int t = blockIdx.x;
    const float* xs = x + (size_t)t * BATCH * DIM;
    __half* o = g_xT + (size_t)t * BATCH * XW;
    for (int i = threadIdx.x; i < BATCH * XW; i += 256) {
        int b = i >> 7, k = i & 127;
        float v = (t < T_STEPS && k < DIM) ? xs[b * DIM + k] : 0.0f;
        o[i] = __float2half_rn(v);
    }
}

// ---------------- kernel 2: persistent RNN, rotated groups + ready-mask polls ----------------
__global__ void __launch_bounds__(NTH, 1)
rnn_kernel(const float* __restrict__ W_ih, const float* __restrict__ b_ih,
           const float* __restrict__ W_hh, const float* __restrict__ b_hh,
           const float* __restrict__ W_out, const float* __restrict__ b_out,
           float* __restrict__ out)
{
    extern __shared__ char smem[];
    __half* sW    = (__half*)(smem + SMEM_W_OFF);
    float*  sBias = (float*)(smem + SMEM_BIAS_OFF);

    const int tid  = threadIdx.x;
    const int blk  = blockIdx.x;
    const int j0   = blk * JT;
    const int lane = tid & 31;
    const int warp = tid >> 5;

    // ---- prologue: W slice fp16 (zero pads first) ----
    for (int i = tid; i < (JT * WPITCH_B) / 4; i += NTH)
        ((uint32_t*)sW)[i] = 0u;
    __syncthreads();
    for (int i = tid; i < JT * HID; i += NTH) {
        int n = i >> 10, k = i & 1023;
        sW[n * WPITCH_H + k] = __float2half_rn(W_hh[(j0 + n) * HID + k]);
    }
    for (int i = tid; i < JT * DIM; i += NTH) {
        int n = i / DIM, d = i % DIM;
        sW[n * WPITCH_H + HID + d] = __float2half_rn(W_ih[(j0 + n) * DIM + d]);
    }
    if (tid < JT) sBias[tid] = b_ih[j0 + tid] + b_hh[j0 + tid];

    // zero h buffer 0: 16384 uint4 == grid*block threads
    {
        uint4 z = make_uint4(0u, 0u, 0u, 0u);
        ((uint4*)g_h[0])[blk * NTH + tid] = z;
    }
    grid_barrier();

    // ---- per-warp geometry: warp owns batch rows [16w,16w+16), cols [j0,j0+16) ----
    uint32_t smem_u = (uint32_t)__cvta_generic_to_shared(smem);
    const uint32_t aslot = smem_u + warp * (NSLOT * AW_B);
    const uint32_t aoff = (lane & 15) * APITCH_B + ((lane >> 4) * 16);
    const uint32_t boff = smem_u + SMEM_W_OFF
        + ((lane & 7) + ((lane & 16) >> 1)) * WPITCH_B + (((lane >> 3) & 1) * 16);

    const int er  = lane >> 2;            // epilogue row within m16
    const int ecc = (lane & 3) * 2;       // epilogue col pair
    const int grow = 16 * warp;           // global batch row base
    const int jc  = j0 + ecc;
    const int gp  = blk >> 3;             // producer group of this block (8 blocks/group)
    const int rot = blk & 7;              // rotated start group
    unsigned* mycnt = &g_cnt[warp * 32 + gp];
    const unsigned* pollbase = &g_cnt[warp * 32];

    const float bia0 = sBias[ecc],     bib0 = sBias[ecc + 1];
    const float bia1 = sBias[ecc + 8], bib1 = sBias[ecc + 9];

    // issue x_0 into SLOT_X
    {
        const __half* hx = g_xT + grow * XW;
        #pragma unroll
        for (int i = 0; i < 8; ++i) {
            int lin = i * 32 + lane;
            int row = lin >> 4, cc = lin & 15;
            cp16(aslot + SLOT_X * AW_B + row * APITCH_B + cc * 16, hx + row * XW + cc * 8);
        }
        cp_commit();
    }

    // ---- time loop ----
    for (int t = 0; t < T_STEPS; ++t) {
        const __half* hrow = g_h[t % 3] + grow * HID;
        __half* hnxt = g_h[(t + 1) % 3];
        const unsigned tgt = 8u * (unsigned)t;

        float acc[16];
        #pragma unroll
        for (int i = 0; i < 16; ++i) acc[i] = 0.0f;

        // compute x chunk (resident from prefetch); overlaps producer tail latency
        cp_wait<0>();
        {
            uint32_t ab = aslot + SLOT_X * AW_B + aoff;
            uint32_t bb = boff + HID * 2;
            #pragma unroll
            for (int s = 0; s < 8; ++s) {
                uint32_t a0, a1, a2, a3, b0, b1, b2, b3;
                ldsm_x4(bb + s * 32, b0, b1, b2, b3);
                ldsm_x4(ab + s * 32, a0, a1, a2, a3);
                float* ac = acc + (s & 1) * 8;
                mma16816(ac + 0, a0, a1, a2, a3, b0, b1);
                mma16816(ac + 4, a0, a1, a2, a3, b2, b3);
            }
        }

        // ready-mask: bit g set when group g of step t-1 fully published
        unsigned mask = (t == 0) ? 0xFFu : 0u;

        // ensure group g ready (refresh mask with one warp-wide L2 read per retry)
        #define ENSURE(gg) while (!((mask >> (gg)) & 1u)) {                         \
            unsigned v_ = (lane < 8) ? ld_acq(pollbase + lane) : 0u;                \
            mask |= __ballot_sync(0xFFFFFFFFu, (lane < 8) && (v_ >= tgt)) & 0xFFu;  \
        }

        // issue first 4 groups in rotated order into slots 0..3
        #pragma unroll
        for (int j = 0; j < 4; ++j) {
            const int g = (rot + j) & 7;
            ENSURE(g);
            const __half* src = hrow + g * KC;
            uint32_t sb = aslot + j * AW_B;
            #pragma unroll
            for (int i = 0; i < 8; ++i) {
                int lin = i * 32 + lane;
                int row = lin >> 4, cc = lin & 15;
                cp16(sb + row * APITCH_B + cc * 16, src + row * HID + cc * 8);
            }
            cp_commit();
        }

        // compute groups in rotated order; prefetch remaining + next x
        #pragma unroll
        for (int j = 0; j < 8; ++j) {
            if (j <= 5)      cp_wait<3>();
            else if (j == 6) cp_wait<2>();
            else             cp_wait<1>();

            const int g = (rot + j) & 7;
            uint32_t ab = aslot + (j & 3) * AW_B + aoff;
            uint32_t bb = boff + g * 256;
            #pragma unroll
            for (int s = 0; s < 8; ++s) {
                uint32_t a0, a1, a2, a3, b0, b1, b2, b3;
                ldsm_x4(bb + s * 32, b0, b1, b2, b3);
                ldsm_x4(ab + s * 32, a0, a1, a2, a3);
                float* ac = acc + (s & 1) * 8;
                mma16816(ac + 0, a0, a1, a2, a3, b0, b1);
                mma16816(ac + 4, a0, a1, a2, a3, b2, b3);
            }

            if (j < 4) {
                const int gn = (rot + j + 4) & 7;
                ENSURE(gn);
                const __half* src = hrow + gn * KC;
                uint32_t sb = aslot + (j & 3) * AW_B;   // slot just freed
                #pragma unroll
                for (int i = 0; i < 8; ++i) {
                    int lin = i * 32 + lane;
                    int row = lin >> 4, cc = lin & 15;
                    cp16(sb + row * APITCH_B + cc * 16, src + row * HID + cc * 8);
                }
                cp_commit();
            } else if (j == 4) {
                const __half* hx = g_xT + (size_t)(t + 1) * (BATCH * XW) + grow * XW;
                #pragma unroll
                for (int i = 0; i < 8; ++i) {
                    int lin = i * 32 + lane;
                    int row = lin >> 4, cc = lin & 15;
                    cp16(aslot + SLOT_X * AW_B + row * APITCH_B + cc * 16, hx + row * XW + cc * 8);
                }
                cp_commit();
            }
        }
        #undef ENSURE

        // ---- epilogue: merge split chains, bias + tanh + fp16 store ----
        {
            int row = grow + er;
            float h0 = tanhf(acc[0] + acc[8]  + bia0);
            float h1 = tanhf(acc[1] + acc[9]  + bib0);
            float h2 = tanhf(acc[2] + acc[10] + bia0);
            float h3 = tanhf(acc[3] + acc[11] + bib0);
            float h4 = tanhf(acc[4] + acc[12] + bia1);
            float h5 = tanhf(acc[5] + acc[13] + bib1);
            float h6 = tanhf(acc[6] + acc[14] + bia1);
            float h7 = tanhf(acc[7] + acc[15] + bib1);
            *reinterpret_cast<__half2*>(&hnxt[row * HID + jc])           = __floats2half2_rn(h0, h1);
            *reinterpret_cast<__half2*>(&hnxt[(row + 8) * HID + jc])     = __floats2half2_rn(h2, h3);
            *reinterpret_cast<__half2*>(&hnxt[row * HID + jc + 8])       = __floats2half2_rn(h4, h5);
            *reinterpret_cast<__half2*>(&hnxt[(row + 8) * HID + jc + 8]) = __floats2half2_rn(h6, h7);
            if (t == T_STEPS - 1) {
                g_hlast[row * HID + jc]           = h0;
                g_hlast[row * HID + jc + 1]       = h1;
                g_hlast[(row + 8) * HID + jc]     = h2;
                g_hlast[(row + 8) * HID + jc + 1] = h3;
                g_hlast[row * HID + jc + 8]       = h4;
                g_hlast[row * HID + jc + 9]       = h5;
                g_hlast[(row + 8) * HID + jc + 8] = h6;
                g_hlast[(row + 8) * HID + jc + 9] = h7;
            }
        }

        // publish this warp's band of step t
        __syncwarp();
        if (lane == 0) {
            asm volatile("red.release.gpu.global.add.u32 [%0], %1;"
                         :: "l"(mycnt), "r"(1u) : "memory");
        }
    }

    // ---- drain, reset counters, readout ----
    grid_barrier();
    if (blk == 0) {
        g_cnt[tid] = 0u;   // 256 threads cover all 256 counter words
        for (int b = warp; b < BATCH; b += 8) {
            float a = 0.0f;
            #pragma unroll 4
            for (int j = lane; j < HID; j += 32)
                a += g_hlast[b * HID + j] * W_out[j];
            #pragma unroll
            for (int o = 16; o; o >>= 1) a += __shfl_xor_sync(0xFFFFFFFFu, a, o);
            if (lane == 0) out[b] = tanhf(a + b_out[0]);
        }
    }
}

// ---------------- launch ----------------
extern "C" void kernel_launch(void* const* d_in, const int* in_sizes, int n_in,
                              void* d_out, int out_size) {
    const float* x     = (const float*)d_in[0];
    const float* W_ih  = (const float*)d_in[1];
    const float* b_ih  = (const float*)d_in[2];
    const float* W_hh  = (const float*)d_in[3];
    const float* b_hh  = (const float*)d_in[4];
    const float* W_out = (const float*)d_in[5];
    const float* b_out = (const float*)d_in[6];

    cudaFuncSetAttribute(rnn_kernel, cudaFuncAttributeMaxDynamicSharedMemorySize, SMEM_TOTAL);

    xform_kernel<<<T_STEPS + 1, 256>>>(x);
    rnn_kernel<<<NBLK, NTH, SMEM_TOTAL>>>(W_ih, b_ih, W_hh, b_hh, W_out, b_out, (float*)d_out);
}